// round 1
// baseline (speedup 1.0000x reference)
#include <cuda_runtime.h>
#include <cstdint>
#include <math.h>

// ============================================================================
// Scratch (allocation-free rule: __device__ globals)
// ============================================================================
__device__ float g_q[4096 * 2048];
__device__ float g_k[4096 * 1024];
__device__ float g_v[4096 * 1024];
__device__ float g_x[4096 * 2048];

// ============================================================================
// Packed fp32x2 FMA (Blackwell full-rate FP32 path; 3-reg FFMA is half rate)
// ============================================================================
__device__ __forceinline__ void ffma2(unsigned long long& d,
                                      unsigned long long a,
                                      unsigned long long b) {
    asm volatile("fma.rn.f32x2 %0, %1, %2, %0;" : "+l"(d) : "l"(a), "l"(b));
}

// ============================================================================
// SGEMM: C[M,N] = A[M,K] @ W[N,K]^T + bias[N]   (both operands K-contiguous)
// 128x128 tile, BK=16, 256 threads, 8x8 per thread, FFMA2 inner loop.
// A tile stored in smem as duplicated float2 pairs so no per-step packing.
// Requires M%128==0, N%128==0, K%16==0 (true for all our shapes).
// ============================================================================
#define BM 128
#define BN 128
#define BK 16

__global__ __launch_bounds__(256, 2)
void sgemm_tn_bias(const float* __restrict__ A, const float* __restrict__ W,
                   const float* __restrict__ bias, float* __restrict__ C,
                   int M, int N, int K)
{
    __shared__ float2 sA[BK][BM];   // duplicated pairs (16 KB)
    __shared__ float  sB[BK][BN];   // 8 KB

    const int tid  = threadIdx.x;
    const int bm   = blockIdx.y * BM;
    const int bn   = blockIdx.x * BN;

    const int wid  = tid >> 5, lane = tid & 31;
    // lane swizzle: warp covers 8 tx x 4 ty -> fewer smem conflicts
    const int tx   = (lane & 7) + ((wid & 1) << 3);   // 0..15
    const int ty   = (lane >> 3) + ((wid >> 1) << 2); // 0..15
    const int m0   = ty * 8;
    const int n0   = tx * 8;

    const int lrow = tid >> 2;        // 0..63
    const int lseg = (tid & 3) << 2;  // 0,4,8,12

    const float* Aptr = A + (size_t)(bm + lrow) * K + lseg;
    const float* Wptr = W + (size_t)(bn + lrow) * K + lseg;

    unsigned long long acc[8][4];
#pragma unroll
    for (int i = 0; i < 8; i++)
#pragma unroll
        for (int j = 0; j < 4; j++) acc[i][j] = 0ull;

    // prefetch tile 0 into registers
    float4 pa0 = *(const float4*)(Aptr);
    float4 pa1 = *(const float4*)(Aptr + (size_t)64 * K);
    float4 pb0 = *(const float4*)(Wptr);
    float4 pb1 = *(const float4*)(Wptr + (size_t)64 * K);

    const int ntiles = K / BK;
    for (int kt = 0; kt < ntiles; kt++) {
        // commit prefetched tile to smem
        {
            const int r0 = lrow, r1 = lrow + 64;
            sA[lseg + 0][r0] = make_float2(pa0.x, pa0.x);
            sA[lseg + 1][r0] = make_float2(pa0.y, pa0.y);
            sA[lseg + 2][r0] = make_float2(pa0.z, pa0.z);
            sA[lseg + 3][r0] = make_float2(pa0.w, pa0.w);
            sA[lseg + 0][r1] = make_float2(pa1.x, pa1.x);
            sA[lseg + 1][r1] = make_float2(pa1.y, pa1.y);
            sA[lseg + 2][r1] = make_float2(pa1.z, pa1.z);
            sA[lseg + 3][r1] = make_float2(pa1.w, pa1.w);
            sB[lseg + 0][r0] = pb0.x;  sB[lseg + 1][r0] = pb0.y;
            sB[lseg + 2][r0] = pb0.z;  sB[lseg + 3][r0] = pb0.w;
            sB[lseg + 0][r1] = pb1.x;  sB[lseg + 1][r1] = pb1.y;
            sB[lseg + 2][r1] = pb1.z;  sB[lseg + 3][r1] = pb1.w;
        }
        __syncthreads();

        if (kt + 1 < ntiles) {
            const float* Ap = Aptr + (size_t)(kt + 1) * BK;
            const float* Wp = Wptr + (size_t)(kt + 1) * BK;
            pa0 = *(const float4*)(Ap);
            pa1 = *(const float4*)(Ap + (size_t)64 * K);
            pb0 = *(const float4*)(Wp);
            pb1 = *(const float4*)(Wp + (size_t)64 * K);
        }

#pragma unroll
        for (int kk = 0; kk < BK; kk++) {
            unsigned long long a[8];
#pragma unroll
            for (int i = 0; i < 8; i += 2) {
                ulonglong2 t2 = *(const ulonglong2*)&sA[kk][m0 + i];
                a[i] = t2.x;  a[i + 1] = t2.y;
            }
            ulonglong2 b0 = *(const ulonglong2*)&sB[kk][n0];
            ulonglong2 b1 = *(const ulonglong2*)&sB[kk][n0 + 4];
            unsigned long long bp0 = b0.x, bp1 = b0.y, bp2 = b1.x, bp3 = b1.y;
#pragma unroll
            for (int i = 0; i < 8; i++) {
                ffma2(acc[i][0], a[i], bp0);
                ffma2(acc[i][1], a[i], bp1);
                ffma2(acc[i][2], a[i], bp2);
                ffma2(acc[i][3], a[i], bp3);
            }
        }
        __syncthreads();
    }

    // epilogue
#pragma unroll
    for (int i = 0; i < 8; i++) {
        float* Crow = C + (size_t)(bm + m0 + i) * N + bn + n0;
#pragma unroll
        for (int j = 0; j < 4; j++) {
            float2 p = *(float2*)&acc[i][j];
            p.x += bias[bn + n0 + 2 * j];
            p.y += bias[bn + n0 + 2 * j + 1];
            *(float2*)&Crow[2 * j] = p;
        }
    }
}

// ============================================================================
// Per-token kernel: RoPE + normalize + random features + kv outer product +
// per-token output, scatter-written in the reference's (buggy) reshape layout:
//   X[b, h*128 + s/16, (s%16)*128 + d] = out[b,h,s,d]
// One block per token (B*S = 4096 blocks), 256 threads, ~125 KB dyn smem.
// ============================================================================
// smem layout (floats):
//   sRt : 128*65   (R transposed, padded: sRt[d*65+e] = R[e,d])
//   sKV : 128*129  (kv[d][f], padded stride 129)
//   sK  : 8*128    sV: 8*128   sKP: 8*128
//   sQ  : 16*128   sQP: 16*128
//   sInvF: 64      sNk: 8      sNq: 16
#define TOK_SMEM_FLOATS (128*65 + 128*129 + 1024*3 + 2048*2 + 64 + 8 + 16)

__global__ __launch_bounds__(256)
void token_kernel(const float* __restrict__ gq, const float* __restrict__ gk,
                  const float* __restrict__ gv, const float* __restrict__ R,
                  float* __restrict__ gx)
{
    extern __shared__ float sm[];
    float* sRt  = sm;                  // 8320
    float* sKV  = sRt + 128 * 65;      // 16512
    float* sK   = sKV + 128 * 129;     // 1024
    float* sV   = sK + 1024;           // 1024
    float* sKP  = sV + 1024;           // 1024
    float* sQ   = sKP + 1024;          // 2048
    float* sQP  = sQ + 2048;           // 2048
    float* sInvF = sQP + 2048;         // 64
    float* sNk  = sInvF + 64;          // 8
    float* sNq  = sNk + 8;             // 16

    const int t     = threadIdx.x;
    const int w     = t >> 5, lane = t & 31;
    const int token = blockIdx.x;
    const int b     = token >> 11;
    const int s     = token & 2047;
    const float INV_SQRT_F = 0.08838834764831845f;  // 1/sqrt(128)

    // R transposed into smem (coalesced gmem read, conflict-free smem write)
    for (int i = t; i < 64 * 128; i += 256) {
        int e = i >> 7, d = i & 127;      // i = e*128 + d (R row-major)
        sRt[d * 65 + e] = R[i];
    }
    // inv_freq[j] = 10000^(-j/64);  ln(10000)/64 = 0.14391156831212787
    if (t < 64) sInvF[t] = (float)exp(-(double)t * 0.14391156831212787);
    __syncthreads();

    // ---- K/V load + RoPE(K) ----
    {
        const int base = token * 1024;
        for (int i = t; i < 1024; i += 256) {
            int d = i & 127;
            float val = gk[base + i];
            float oth = gk[base + (i & ~127) + ((d < 64) ? d + 64 : d - 64)];
            float ang = (float)s * sInvF[d & 63];
            float sn, cs;  sincosf(ang, &sn, &cs);
            sK[i] = val * cs + ((d < 64) ? -oth : oth) * sn;
            sV[i] = gv[base + i];
        }
    }
    __syncthreads();

    // ---- K norms: warp w handles kv-head w ----
    if (w < 8) {
        float ss = 0.f;
#pragma unroll
        for (int d = lane; d < 128; d += 32) { float x = sK[w * 128 + d]; ss += x * x; }
#pragma unroll
        for (int o = 16; o; o >>= 1) ss += __shfl_xor_sync(0xffffffffu, ss, o);
        if (lane == 0) sNk[w] = fmaxf(sqrtf(ss), 1e-6f);
    }
    __syncthreads();

    // ---- K projection + sin/cos features (8 heads x 64 proj dims) ----
#pragma unroll
    for (int it = 0; it < 2; it++) {
        int idx = it * 256 + t;
        int i = idx >> 6, e = idx & 63;
        const float* kr = sK + i * 128;
        float acc = 0.f;
#pragma unroll 4
        for (int d = 0; d < 128; d++) acc += kr[d] * sRt[d * 65 + e];
        float p = acc / sNk[i];
        float sp, cp;  sincosf(p, &sp, &cp);
        sKP[i * 128 + e]      = sp * INV_SQRT_F;
        sKP[i * 128 + e + 64] = cp * INV_SQRT_F;
    }
    __syncthreads();

    // ---- kv[d][f] = 2 * sum_i kp[i][f] * v[i][d] ----
    {
        int f  = t & 127;
        int d0 = (t >> 7) << 6;
        float kp[8];
#pragma unroll
        for (int i = 0; i < 8; i++) kp[i] = sKP[i * 128 + f];
        for (int d = d0; d < d0 + 64; d++) {
            float acc = 0.f;
#pragma unroll
            for (int i = 0; i < 8; i++) acc += kp[i] * sV[i * 128 + d];
            sKV[d * 129 + f] = 2.0f * acc;
        }
    }

    // ---- Q load + RoPE (independent smem arrays; sync comes after) ----
    {
        const int base = token * 2048;
        for (int i = t; i < 2048; i += 256) {
            int d = i & 127;
            float val = gq[base + i];
            float oth = gq[base + (i & ~127) + ((d < 64) ? d + 64 : d - 64)];
            float ang = (float)s * sInvF[d & 63];
            float sn, cs;  sincosf(ang, &sn, &cs);
            sQ[i] = val * cs + ((d < 64) ? -oth : oth) * sn;
        }
    }
    __syncthreads();

    // ---- Q norms: warp w handles heads w and w+8 ----
#pragma unroll
    for (int hh = w; hh < 16; hh += 8) {
        float ss = 0.f;
#pragma unroll
        for (int d = lane; d < 128; d += 32) { float x = sQ[hh * 128 + d]; ss += x * x; }
#pragma unroll
        for (int o = 16; o; o >>= 1) ss += __shfl_xor_sync(0xffffffffu, ss, o);
        if (lane == 0) sNq[hh] = fmaxf(sqrtf(ss), 1e-6f);
    }
    __syncthreads();

    // ---- Q projection + features (16 heads x 64) ----
#pragma unroll
    for (int it = 0; it < 4; it++) {
        int idx = it * 256 + t;
        int h = idx >> 6, e = idx & 63;
        const float* qr = sQ + h * 128;
        float acc = 0.f;
#pragma unroll 4
        for (int d = 0; d < 128; d++) acc += qr[d] * sRt[d * 65 + e];
        float p = acc / sNq[h];
        float sp, cp;  sincosf(p, &sp, &cp);
        sQP[h * 128 + e]      = sp * INV_SQRT_F;
        sQP[h * 128 + e + 64] = cp * INV_SQRT_F;
    }
    __syncthreads();

    // ---- out[h][d] = sum_f qp[h][f] * kv[d][f]; scatter in reshape layout ----
    {
        int d  = t & 127;
        int h0 = (t >> 7) << 3;
        float acc[8];
#pragma unroll
        for (int j = 0; j < 8; j++) acc[j] = 0.f;
        const float* kvd = sKV + d * 129;
        for (int f = 0; f < 128; f += 4) {
            float k0 = kvd[f], k1 = kvd[f + 1], k2 = kvd[f + 2], k3 = kvd[f + 3];
#pragma unroll
            for (int j = 0; j < 8; j++) {
                const float4 q4 = *(const float4*)&sQP[(h0 + j) * 128 + f];
                acc[j] += q4.x * k0 + q4.y * k1 + q4.z * k2 + q4.w * k3;
            }
        }
        // reference reshapes (b,H,s,D)->(b,s,HID) WITHOUT transpose:
        // row = h*128 + s/16, col = (s%16)*128 + d
        const size_t obase = ((size_t)b << 22) + (size_t)((s & 15) << 7) + d;
        const int rlo = s >> 4;
#pragma unroll
        for (int j = 0; j < 8; j++) {
            int h = h0 + j;
            gx[obase + (size_t)(h * 128 + rlo) * 2048] = acc[j];
        }
    }
}

// ============================================================================
// Launch
// ============================================================================
extern "C" void kernel_launch(void* const* d_in, const int* in_sizes, int n_in,
                              void* d_out, int out_size)
{
    const float* hs = (const float*)d_in[0];
    const float* Wq = (const float*)d_in[1];
    const float* bq = (const float*)d_in[2];
    const float* Wk = (const float*)d_in[3];
    const float* bk = (const float*)d_in[4];
    const float* Wv = (const float*)d_in[5];
    const float* bv = (const float*)d_in[6];
    const float* Wo = (const float*)d_in[7];
    const float* bo = (const float*)d_in[8];
    const float* R  = (const float*)d_in[9];
    float* out = (float*)d_out;
    (void)in_sizes; (void)n_in; (void)out_size;

    float *q, *k, *v, *x;
    cudaGetSymbolAddress((void**)&q, g_q);
    cudaGetSymbolAddress((void**)&k, g_k);
    cudaGetSymbolAddress((void**)&v, g_v);
    cudaGetSymbolAddress((void**)&x, g_x);

    const size_t tok_smem = TOK_SMEM_FLOATS * sizeof(float);
    cudaFuncSetAttribute(token_kernel,
                         cudaFuncAttributeMaxDynamicSharedMemorySize,
                         (int)tok_smem);

    // QKV projections
    sgemm_tn_bias<<<dim3(2048 / BN, 4096 / BM), 256>>>(hs, Wq, bq, q, 4096, 2048, 2048);
    sgemm_tn_bias<<<dim3(1024 / BN, 4096 / BM), 256>>>(hs, Wk, bk, k, 4096, 1024, 2048);
    sgemm_tn_bias<<<dim3(1024 / BN, 4096 / BM), 256>>>(hs, Wv, bv, v, 4096, 1024, 2048);

    // Per-token performer core
    token_kernel<<<4096, 256, tok_smem>>>(q, k, v, R, x);

    // Output projection
    sgemm_tn_bias<<<dim3(2048 / BN, 4096 / BM), 256>>>(x, Wo, bo, out, 4096, 2048, 2048);
}

// round 3
// speedup vs baseline: 3.0718x; 3.0718x over previous
#include <cuda_runtime.h>
#include <cuda_bf16.h>
#include <cstdint>
#include <math.h>

// ============================================================================
// Scratch (allocation-free rule: __device__ globals)
// ============================================================================
__device__ float g_q[4096 * 2048];
__device__ float g_k[4096 * 1024];
__device__ float g_v[4096 * 1024];
__device__ unsigned short g_hsh[4096 * 2048], g_hsl[4096 * 2048];
__device__ unsigned short g_wqh[2048 * 2048], g_wql[2048 * 2048];
__device__ unsigned short g_wkh[1024 * 2048], g_wkl[1024 * 2048];
__device__ unsigned short g_wvh[1024 * 2048], g_wvl[1024 * 2048];
__device__ unsigned short g_woh[2048 * 2048], g_wol[2048 * 2048];
__device__ unsigned short g_xh[4096 * 2048], g_xl[4096 * 2048];

// ============================================================================
// Helpers
// ============================================================================
__device__ __forceinline__ uint32_t smem_u32(const void* p) {
    uint32_t a;
    asm("{ .reg .u64 t; cvta.to.shared.u64 t, %1; cvt.u32.u64 %0, t; }" : "=r"(a) : "l"(p));
    return a;
}
__device__ __forceinline__ void cp16(uint32_t soff, const void* g) {
    asm volatile("cp.async.cg.shared.global [%0], [%1], 16;" :: "r"(soff), "l"(g));
}
__device__ __forceinline__ void cp_commit() { asm volatile("cp.async.commit_group;"); }
__device__ __forceinline__ void cp_wait0()  { asm volatile("cp.async.wait_group 0;" ::: "memory"); }
__device__ __forceinline__ void cp_wait1()  { asm volatile("cp.async.wait_group 1;" ::: "memory"); }

__device__ __forceinline__ void ldm_x4(uint32_t* r, uint32_t addr) {
    asm volatile("ldmatrix.sync.aligned.m8n8.x4.shared.b16 {%0,%1,%2,%3}, [%4];"
                 : "=r"(r[0]), "=r"(r[1]), "=r"(r[2]), "=r"(r[3]) : "r"(addr));
}
__device__ __forceinline__ void mma16816(float* c, const uint32_t* a, const uint32_t* b) {
    asm volatile(
        "mma.sync.aligned.m16n8k16.row.col.f32.bf16.bf16.f32 "
        "{%0,%1,%2,%3}, {%4,%5,%6,%7}, {%8,%9}, {%0,%1,%2,%3};"
        : "+f"(c[0]), "+f"(c[1]), "+f"(c[2]), "+f"(c[3])
        : "r"(a[0]), "r"(a[1]), "r"(a[2]), "r"(a[3]), "r"(b[0]), "r"(b[1]));
}

// ============================================================================
// fp32 -> (bf16 hi, bf16 lo) split
// ============================================================================
__global__ __launch_bounds__(256)
void split_kernel(const float* __restrict__ in, unsigned short* __restrict__ hi,
                  unsigned short* __restrict__ lo, int n4)
{
    int i = blockIdx.x * 256 + threadIdx.x;
    if (i >= n4) return;
    float4 x = ((const float4*)in)[i];
    __nv_bfloat16 h0 = __float2bfloat16_rn(x.x);
    __nv_bfloat16 h1 = __float2bfloat16_rn(x.y);
    __nv_bfloat16 h2 = __float2bfloat16_rn(x.z);
    __nv_bfloat16 h3 = __float2bfloat16_rn(x.w);
    __nv_bfloat16 l0 = __float2bfloat16_rn(x.x - __bfloat162float(h0));
    __nv_bfloat16 l1 = __float2bfloat16_rn(x.y - __bfloat162float(h1));
    __nv_bfloat16 l2 = __float2bfloat16_rn(x.z - __bfloat162float(h2));
    __nv_bfloat16 l3 = __float2bfloat16_rn(x.w - __bfloat162float(h3));
    ushort4 H, L;
    H.x = *(unsigned short*)&h0;  H.y = *(unsigned short*)&h1;
    H.z = *(unsigned short*)&h2;  H.w = *(unsigned short*)&h3;
    L.x = *(unsigned short*)&l0;  L.y = *(unsigned short*)&l1;
    L.z = *(unsigned short*)&l2;  L.w = *(unsigned short*)&l3;
    ((ushort4*)hi)[i] = H;
    ((ushort4*)lo)[i] = L;
}

// ============================================================================
// mma.sync bf16x3 GEMM:  C[M,N] = (Ah+Al)[M,K] @ (Bh+Bl)[N,K]^T + bias[N]
// 128x128x32 tile, 256 threads, 8 warps (2m x 4n), warp tile 64x32,
// 2-stage cp.async pipeline, ldmatrix fragments, 3 MMA terms (hh, hl, lh).
// ============================================================================
#define GBM 128
#define GBN 128
#define GBK 32
#define APITCH 40                       // bf16 elems per smem row (80 B, conflict-free)
#define TILE_B (128 * APITCH * 2)       // 10240 bytes per tile
#define STAGE_B (4 * TILE_B)            // Ah | Al | Bh | Bl = 40960 bytes
#define GEMM_SMEM (2 * STAGE_B)         // 81920 bytes

__global__ __launch_bounds__(256, 1)
void gemm_bf16x3(const unsigned short* __restrict__ Ah, const unsigned short* __restrict__ Al,
                 const unsigned short* __restrict__ Bh, const unsigned short* __restrict__ Bl,
                 const float* __restrict__ bias, float* __restrict__ C,
                 int M, int N, int K)
{
    extern __shared__ __align__(128) char smem[];
    const uint32_t sb = smem_u32(smem);
    const int tid = threadIdx.x, wid = tid >> 5, lane = tid & 31;
    const int bm = blockIdx.y * GBM, bn = blockIdx.x * GBN;
    const int m0w = (wid & 1) * 64, n0w = (wid >> 1) * 32;

    float c[4][4][4];
#pragma unroll
    for (int i = 0; i < 4; i++)
#pragma unroll
        for (int j = 0; j < 4; j++)
#pragma unroll
            for (int r = 0; r < 4; r++) c[i][j][r] = 0.f;

    // fragment lane address components
    const int rowA = lane & 15, kselA = (lane >> 4) * 8;
    const int grpB = lane >> 3, rowB = lane & 7;
    const int nAdd = rowB + ((grpB & 2) ? 8 : 0);
    const int kAdd = (grpB & 1) * 8;

    const int nk = K / GBK;

    // ---- stage loader: 2048 cp16 chunks (4 tiles x 128 rows x 4 chunks) ----
    auto load_stage = [&](int kt, int buf) {
        const int k0 = kt * GBK;
        const uint32_t stb = sb + buf * STAGE_B;
#pragma unroll
        for (int it = 0; it < 8; it++) {
            int cidx = it * 256 + tid;
            int tile = cidx >> 9, idx = cidx & 511, row = idx >> 2, ch = idx & 3;
            uint32_t so = stb + tile * TILE_B + row * (APITCH * 2) + ch * 16;
            const unsigned short* g =
                (tile == 0) ? Ah : (tile == 1) ? Al : (tile == 2) ? Bh : Bl;
            int gr = ((tile < 2) ? bm : bn) + row;
            cp16(so, g + (size_t)gr * K + k0 + ch * 8);
        }
    };

    load_stage(0, 0);
    cp_commit();

    for (int kt = 0; kt < nk; kt++) {
        const int buf = kt & 1;
        if (kt + 1 < nk) {
            load_stage(kt + 1, buf ^ 1);
            cp_commit();
            cp_wait1();
        } else {
            cp_wait0();
        }
        __syncthreads();

        const uint32_t stb = sb + buf * STAGE_B;
        const uint32_t sA = stb;
        const uint32_t sB = stb + 2 * TILE_B;

#pragma unroll
        for (int kb = 0; kb < 2; kb++) {
            const int kcol = kb * 16;
            uint32_t ah[4][4], al[4][4];
#pragma unroll
            for (int i = 0; i < 4; i++) {
                uint32_t addr = sA + ((m0w + 16 * i + rowA) * APITCH + kcol + kselA) * 2;
                ldm_x4(ah[i], addr);
                ldm_x4(al[i], addr + TILE_B);
            }
            uint32_t bh[2][4], bl[2][4];
#pragma unroll
            for (int jj = 0; jj < 2; jj++) {
                uint32_t addr = sB + ((n0w + 16 * jj + nAdd) * APITCH + kcol + kAdd) * 2;
                ldm_x4(bh[jj], addr);
                ldm_x4(bl[jj], addr + TILE_B);
            }
#pragma unroll
            for (int i = 0; i < 4; i++)
#pragma unroll
                for (int j = 0; j < 4; j++) {
                    const uint32_t* ph = &bh[j >> 1][(j & 1) * 2];
                    const uint32_t* pl = &bl[j >> 1][(j & 1) * 2];
                    mma16816(c[i][j], ah[i], ph);
                    mma16816(c[i][j], ah[i], pl);
                    mma16816(c[i][j], al[i], ph);
                }
        }
        __syncthreads();
    }

    // ---- epilogue: direct gmem stores + bias ----
    const int r0 = lane >> 2, cc = (lane & 3) * 2;
#pragma unroll
    for (int i = 0; i < 4; i++) {
#pragma unroll
        for (int j = 0; j < 4; j++) {
            int row = bm + m0w + 16 * i + r0;
            int col = bn + n0w + 8 * j + cc;
            float b0 = bias[col], b1 = bias[col + 1];
            float2 v0 = make_float2(c[i][j][0] + b0, c[i][j][1] + b1);
            float2 v1 = make_float2(c[i][j][2] + b0, c[i][j][3] + b1);
            *(float2*)&C[(size_t)row * N + col]       = v0;
            *(float2*)&C[(size_t)(row + 8) * N + col] = v1;
        }
    }
}

// ============================================================================
// Token kernel: RoPE + normalize + random features + head-contraction trick:
//   out[h,d] = sum_i (2 * sum_f qp[h,f] kp[i,f]) * v[i,d]   (contract f FIRST)
// Emits bf16 hi/lo splits directly in the reference's reshape-quirk layout:
//   X[b, h*128 + s/16, (s%16)*128 + d]
// ============================================================================
#define TOKF (8320 + 64 + 64 + 1024 + 1024 + 2048 + 1032 + 2064 + 24 + 128)

__global__ __launch_bounds__(256)
void token_kernel(const float* __restrict__ gq, const float* __restrict__ gk,
                  const float* __restrict__ gv, const float* __restrict__ R,
                  unsigned short* __restrict__ gxh, unsigned short* __restrict__ gxl)
{
    extern __shared__ float sm[];
    float* sRt  = sm;               // 128*65
    float* sSin = sRt + 8320;       // 64
    float* sCos = sSin + 64;        // 64
    float* sK   = sCos + 64;        // 1024
    float* sV   = sK + 1024;        // 1024
    float* sQ   = sV + 1024;        // 2048
    float* sKP  = sQ + 2048;        // 8*129
    float* sQP  = sKP + 1032;       // 16*129
    float* sN   = sQP + 2064;       // 24
    float* sA   = sN + 24;          // 128

    const int t = threadIdx.x, w = t >> 5, lane = t & 31;
    const int token = blockIdx.x, b = token >> 11, s = token & 2047;
    const float INVSF = 0.08838834764831845f;  // 1/sqrt(128)

    for (int i = t; i < 8192; i += 256) {
        int e = i >> 7, d = i & 127;
        sRt[d * 65 + e] = R[i];
    }
    if (t < 64) {
        float iv = (float)exp(-(double)t * 0.14391156831212787);  // ln(1e4)/64
        float ang = (float)s * iv;
        sincosf(ang, &sSin[t], &sCos[t]);
    }
    __syncthreads();

    // K/V/Q loads + RoPE
    {
        const int base = token * 1024;
        for (int i = t; i < 1024; i += 256) {
            int d = i & 127, j = d & 63;
            float val = gk[base + i];
            float oth = gk[base + (i & ~127) + ((d < 64) ? d + 64 : d - 64)];
            sK[i] = val * sCos[j] + ((d < 64) ? -oth : oth) * sSin[j];
            sV[i] = gv[base + i];
        }
        const int b2 = token * 2048;
        for (int i = t; i < 2048; i += 256) {
            int d = i & 127, j = d & 63;
            float val = gq[b2 + i];
            float oth = gq[b2 + (i & ~127) + ((d < 64) ? d + 64 : d - 64)];
            sQ[i] = val * sCos[j] + ((d < 64) ? -oth : oth) * sSin[j];
        }
    }
    __syncthreads();

    // norms: rows 0-7 = K heads, 8-23 = Q heads
    for (int r = w; r < 24; r += 8) {
        const float* src = (r < 8) ? sK + r * 128 : sQ + (r - 8) * 128;
        float ss = 0.f;
        for (int d = lane; d < 128; d += 32) { float x = src[d]; ss += x * x; }
#pragma unroll
        for (int o = 16; o; o >>= 1) ss += __shfl_xor_sync(0xffffffffu, ss, o);
        if (lane == 0) sN[r] = fmaxf(sqrtf(ss), 1e-6f);
    }
    __syncthreads();

    // projection + sin/cos features: 24 rows x 64 proj dims
#pragma unroll
    for (int it = 0; it < 6; it++) {
        int idx = it * 256 + t;
        int r = idx >> 6, e = idx & 63;
        const float* src = (r < 8) ? sK + r * 128 : sQ + (r - 8) * 128;
        float acc = 0.f;
#pragma unroll 8
        for (int d = 0; d < 128; d++) acc += src[d] * sRt[d * 65 + e];
        float p = acc / sN[r];
        float sp, cp;
        __sincosf(p, &sp, &cp);
        float* dst = (r < 8) ? sKP + r * 129 : sQP + (r - 8) * 129;
        dst[e] = sp * INVSF;
        dst[e + 64] = cp * INVSF;
    }
    __syncthreads();

    // scores A[h,i] = 2 * sum_f qp[h,f] kp[i,f]
    if (t < 128) {
        int h = t >> 3, i = t & 7;
        float acc = 0.f;
#pragma unroll 8
        for (int f = 0; f < 128; f++) acc += sQP[h * 129 + f] * sKP[i * 129 + f];
        sA[t] = 2.0f * acc;
    }
    __syncthreads();

    // out[h,d] = sum_i A[h,i] v[i,d], bf16-split, reshape-quirk scatter
    {
        const size_t obase = ((size_t)b << 22) + (size_t)((s & 15) << 7);
        const int rlo = s >> 4;
#pragma unroll
        for (int it = 0; it < 8; it++) {
            int idx = it * 256 + t;
            int h = idx >> 7, d = idx & 127;
            float acc = 0.f;
#pragma unroll
            for (int i = 0; i < 8; i++) acc += sA[h * 8 + i] * sV[i * 128 + d];
            size_t oi = obase + (size_t)(h * 128 + rlo) * 2048 + d;
            __nv_bfloat16 hv = __float2bfloat16_rn(acc);
            __nv_bfloat16 lv = __float2bfloat16_rn(acc - __bfloat162float(hv));
            gxh[oi] = *(unsigned short*)&hv;
            gxl[oi] = *(unsigned short*)&lv;
        }
    }
}

// ============================================================================
// Launch
// ============================================================================
extern "C" void kernel_launch(void* const* d_in, const int* in_sizes, int n_in,
                              void* d_out, int out_size)
{
    const float* hs = (const float*)d_in[0];
    const float* Wq = (const float*)d_in[1];
    const float* bq = (const float*)d_in[2];
    const float* Wk = (const float*)d_in[3];
    const float* bk = (const float*)d_in[4];
    const float* Wv = (const float*)d_in[5];
    const float* bv = (const float*)d_in[6];
    const float* Wo = (const float*)d_in[7];
    const float* bo = (const float*)d_in[8];
    const float* R  = (const float*)d_in[9];
    float* out = (float*)d_out;
    (void)in_sizes; (void)n_in; (void)out_size;

    float *q, *k, *v;
    unsigned short *hsh, *hsl, *wqh, *wql, *wkh, *wkl, *wvh, *wvl, *woh, *wol, *xh, *xl;
    cudaGetSymbolAddress((void**)&q, g_q);
    cudaGetSymbolAddress((void**)&k, g_k);
    cudaGetSymbolAddress((void**)&v, g_v);
    cudaGetSymbolAddress((void**)&hsh, g_hsh);  cudaGetSymbolAddress((void**)&hsl, g_hsl);
    cudaGetSymbolAddress((void**)&wqh, g_wqh);  cudaGetSymbolAddress((void**)&wql, g_wql);
    cudaGetSymbolAddress((void**)&wkh, g_wkh);  cudaGetSymbolAddress((void**)&wkl, g_wkl);
    cudaGetSymbolAddress((void**)&wvh, g_wvh);  cudaGetSymbolAddress((void**)&wvl, g_wvl);
    cudaGetSymbolAddress((void**)&woh, g_woh);  cudaGetSymbolAddress((void**)&wol, g_wol);
    cudaGetSymbolAddress((void**)&xh, g_xh);    cudaGetSymbolAddress((void**)&xl, g_xl);

    cudaFuncSetAttribute(gemm_bf16x3, cudaFuncAttributeMaxDynamicSharedMemorySize, GEMM_SMEM);
    cudaFuncSetAttribute(token_kernel, cudaFuncAttributeMaxDynamicSharedMemorySize,
                         TOKF * (int)sizeof(float));

    // fp32 -> bf16 hi/lo splits
    split_kernel<<<8192, 256>>>(hs, hsh, hsl, 2097152);
    split_kernel<<<4096, 256>>>(Wq, wqh, wql, 1048576);
    split_kernel<<<2048, 256>>>(Wk, wkh, wkl, 524288);
    split_kernel<<<2048, 256>>>(Wv, wvh, wvl, 524288);
    split_kernel<<<4096, 256>>>(Wo, woh, wol, 1048576);

    // QKV projections (mma.sync bf16x3)
    gemm_bf16x3<<<dim3(16, 32), 256, GEMM_SMEM>>>(
        hsh, hsl, wqh, wql, bq, q, 4096, 2048, 2048);
    gemm_bf16x3<<<dim3(8, 32), 256, GEMM_SMEM>>>(
        hsh, hsl, wkh, wkl, bk, k, 4096, 1024, 2048);
    gemm_bf16x3<<<dim3(8, 32), 256, GEMM_SMEM>>>(
        hsh, hsl, wvh, wvl, bv, v, 4096, 1024, 2048);

    // Performer core (writes bf16 splits of X)
    token_kernel<<<4096, 256, TOKF * sizeof(float)>>>(q, k, v, R, xh, xl);

    // Output projection
    gemm_bf16x3<<<dim3(16, 32), 256, GEMM_SMEM>>>(
        xh, xl, woh, wol, bo, out, 4096, 2048, 2048);
}

// round 4
// speedup vs baseline: 4.9843x; 1.6226x over previous
#include <cuda_runtime.h>
#include <cuda_fp16.h>
#include <cstdint>
#include <math.h>

// ============================================================================
// Scratch (allocation-free rule: __device__ globals)
// ============================================================================
__device__ float g_q[4096 * 2048];
__device__ float g_kv[4096 * 2048];           // cols 0-1023 = K, 1024-2047 = V
__device__ unsigned short g_hsh[8388608], g_hsl[8388608];
__device__ unsigned short g_wqh[4194304];
__device__ unsigned short g_wkvh[4194304];    // rows 0-1023 = Wk, 1024-2047 = Wv
__device__ unsigned short g_woh[4194304];
__device__ unsigned short g_xh[8388608], g_xl[8388608];

// ============================================================================
// Helpers
// ============================================================================
__device__ __forceinline__ uint32_t smem_u32(const void* p) {
    uint32_t a;
    asm("{ .reg .u64 t; cvta.to.shared.u64 t, %1; cvt.u32.u64 %0, t; }" : "=r"(a) : "l"(p));
    return a;
}
__device__ __forceinline__ void cp16(uint32_t soff, const void* g) {
    asm volatile("cp.async.cg.shared.global [%0], [%1], 16;" :: "r"(soff), "l"(g));
}
__device__ __forceinline__ void cp_commit() { asm volatile("cp.async.commit_group;"); }
__device__ __forceinline__ void cp_wait0()  { asm volatile("cp.async.wait_group 0;" ::: "memory"); }
__device__ __forceinline__ void cp_wait1()  { asm volatile("cp.async.wait_group 1;" ::: "memory"); }
__device__ __forceinline__ void cp_wait2()  { asm volatile("cp.async.wait_group 2;" ::: "memory"); }

__device__ __forceinline__ void ldm_x4(uint32_t* r, uint32_t addr) {
    asm volatile("ldmatrix.sync.aligned.m8n8.x4.shared.b16 {%0,%1,%2,%3}, [%4];"
                 : "=r"(r[0]), "=r"(r[1]), "=r"(r[2]), "=r"(r[3]) : "r"(addr));
}
__device__ __forceinline__ void mma16816(float* c, const uint32_t* a, const uint32_t* b) {
    asm volatile(
        "mma.sync.aligned.m16n8k16.row.col.f32.f16.f16.f32 "
        "{%0,%1,%2,%3}, {%4,%5,%6,%7}, {%8,%9}, {%0,%1,%2,%3};"
        : "+f"(c[0]), "+f"(c[1]), "+f"(c[2]), "+f"(c[3])
        : "r"(a[0]), "r"(a[1]), "r"(a[2]), "r"(a[3]), "r"(b[0]), "r"(b[1]));
}

// ============================================================================
// fp32 -> (fp16 hi, fp16 lo) split  /  fp32 -> fp16 convert
// ============================================================================
__global__ __launch_bounds__(256)
void split_f16(const float* __restrict__ in, unsigned short* __restrict__ hi,
               unsigned short* __restrict__ lo, int n4)
{
    int i = blockIdx.x * 256 + threadIdx.x;
    if (i >= n4) return;
    float4 x = ((const float4*)in)[i];
    __half h0 = __float2half_rn(x.x), h1 = __float2half_rn(x.y);
    __half h2 = __float2half_rn(x.z), h3 = __float2half_rn(x.w);
    __half l0 = __float2half_rn(x.x - __half2float(h0));
    __half l1 = __float2half_rn(x.y - __half2float(h1));
    __half l2 = __float2half_rn(x.z - __half2float(h2));
    __half l3 = __float2half_rn(x.w - __half2float(h3));
    ushort4 H, L;
    H.x = *(unsigned short*)&h0;  H.y = *(unsigned short*)&h1;
    H.z = *(unsigned short*)&h2;  H.w = *(unsigned short*)&h3;
    L.x = *(unsigned short*)&l0;  L.y = *(unsigned short*)&l1;
    L.z = *(unsigned short*)&l2;  L.w = *(unsigned short*)&l3;
    ((ushort4*)hi)[i] = H;
    ((ushort4*)lo)[i] = L;
}

__global__ __launch_bounds__(256)
void convert_f16(const float* __restrict__ in, unsigned short* __restrict__ hi, int n4)
{
    int i = blockIdx.x * 256 + threadIdx.x;
    if (i >= n4) return;
    float4 x = ((const float4*)in)[i];
    __half h0 = __float2half_rn(x.x), h1 = __float2half_rn(x.y);
    __half h2 = __float2half_rn(x.z), h3 = __float2half_rn(x.w);
    ushort4 H;
    H.x = *(unsigned short*)&h0;  H.y = *(unsigned short*)&h1;
    H.z = *(unsigned short*)&h2;  H.w = *(unsigned short*)&h3;
    ((ushort4*)hi)[i] = H;
}

// ============================================================================
// mma.sync fp16 2-term GEMM:  C[M,N] = (Ah+Al)[M,K] @ Bh[N,K]^T + bias[N]
//   (B truncated to fp16; error ~2^-12, well under the 1e-3 gate)
// Block 128x256x32, 256 threads, 8 warps (2m x 4n), warp tile 64x64.
// 4-stage cp.async pipeline, one __syncthreads per k-tile.
// ============================================================================
#define GBM 128
#define GBN 256
#define GBK 32
#define APITCH 40                       // fp16 elems/row (80 B, ldmatrix conflict-free)
#define ROW_B  (APITCH * 2)             // 80
#define OFF_AL 10240                    // Ah: 128 rows * 80
#define OFF_B  20480                    // Al: 128 rows * 80
#define STAGE_B 40960                   // + Bh: 256 rows * 80
#define NSTAGE 4
#define GEMM_SMEM (NSTAGE * STAGE_B)    // 163840

__global__ __launch_bounds__(256, 1)
void gemm_f16x2(const unsigned short* __restrict__ Ah, const unsigned short* __restrict__ Al,
                const unsigned short* __restrict__ Bh,
                const float* __restrict__ bias0, const float* __restrict__ bias1, int nsplit,
                float* __restrict__ C, int M, int N, int K)
{
    extern __shared__ __align__(128) char smem[];
    const uint32_t sb = smem_u32(smem);
    const int tid = threadIdx.x, wid = tid >> 5, lane = tid & 31;
    const int bm = blockIdx.y * GBM, bn = blockIdx.x * GBN;
    const int m0w = (wid & 1) * 64, n0w = (wid >> 1) * 64;

    float c[4][8][4];
#pragma unroll
    for (int i = 0; i < 4; i++)
#pragma unroll
        for (int j = 0; j < 8; j++)
#pragma unroll
            for (int r = 0; r < 4; r++) c[i][j][r] = 0.f;

    // ldmatrix lane -> address components
    const int rowA = lane & 15, kselA = (lane >> 4) * 8;
    const int grpB = lane >> 3, rowB = lane & 7;
    const int nAdd = rowB + ((grpB & 2) ? 8 : 0);
    const int kAdd = (grpB & 1) * 8;

    const int nk = K / GBK;

    auto load_stage = [&](int kt, int buf) {
        const int k0 = kt * GBK;
        const uint32_t stb = sb + buf * STAGE_B;
#pragma unroll
        for (int it = 0; it < 8; it++) {
            int cc = it * 256 + tid;               // 0..2047
            int tile = cc >> 9;
            int idx = cc & 511, row = idx >> 2, ch = idx & 3;
            uint32_t so;
            const unsigned short* g;
            if (tile == 0)      { so = stb + row * ROW_B + ch * 16;          g = Ah + (size_t)(bm + row) * K; }
            else if (tile == 1) { so = stb + OFF_AL + row * ROW_B + ch * 16; g = Al + (size_t)(bm + row) * K; }
            else {
                int r2 = row + ((tile == 3) ? 128 : 0);
                so = stb + OFF_B + r2 * ROW_B + ch * 16;
                g = Bh + (size_t)(bn + r2) * K;
            }
            cp16(so, g + k0 + ch * 8);
        }
    };

    load_stage(0, 0); cp_commit();
    load_stage(1, 1); cp_commit();
    load_stage(2, 2); cp_commit();

    for (int kt = 0; kt < nk; kt++) {
        if (kt + 3 <= nk)      cp_wait2();
        else if (kt + 2 == nk) cp_wait1();
        else                   cp_wait0();
        __syncthreads();

        const uint32_t stb = sb + (kt & 3) * STAGE_B;
        const uint32_t sA = stb, sB = stb + OFF_B;

#pragma unroll
        for (int kb = 0; kb < 2; kb++) {
            const int kcol = kb * 16;
            uint32_t ah[4][4], al[4][4];
#pragma unroll
            for (int i = 0; i < 4; i++) {
                uint32_t addr = sA + ((m0w + 16 * i + rowA) * APITCH + kcol + kselA) * 2;
                ldm_x4(ah[i], addr);
                ldm_x4(al[i], addr + OFF_AL);
            }
            uint32_t bh[4][4];
#pragma unroll
            for (int jj = 0; jj < 4; jj++) {
                uint32_t addr = sB + ((n0w + 16 * jj + nAdd) * APITCH + kcol + kAdd) * 2;
                ldm_x4(bh[jj], addr);
            }
#pragma unroll
            for (int i = 0; i < 4; i++)
#pragma unroll
                for (int j = 0; j < 8; j++) {
                    const uint32_t* ph = &bh[j >> 1][(j & 1) * 2];
                    mma16816(c[i][j], ah[i], ph);
                    mma16816(c[i][j], al[i], ph);
                }
        }

        if (kt + 3 < nk) { load_stage(kt + 3, (kt + 3) & 3); cp_commit(); }
    }

    // epilogue: direct stores + per-column bias (bias1 for cols >= nsplit)
    const int r0 = lane >> 2, cc2 = (lane & 3) * 2;
#pragma unroll
    for (int i = 0; i < 4; i++) {
#pragma unroll
        for (int j = 0; j < 8; j++) {
            int row = bm + m0w + 16 * i + r0;
            int col = bn + n0w + 8 * j + cc2;
            const float* bp = (col < nsplit) ? bias0 : bias1;
            int cb = (col < nsplit) ? col : col - nsplit;
            float b0 = bp[cb], b1 = bp[cb + 1];
            float2 v0 = make_float2(c[i][j][0] + b0, c[i][j][1] + b1);
            float2 v1 = make_float2(c[i][j][2] + b0, c[i][j][3] + b1);
            *(float2*)&C[(size_t)row * N + col]       = v0;
            *(float2*)&C[(size_t)(row + 8) * N + col] = v1;
        }
    }
}

// ============================================================================
// Token kernel: RoPE + normalize + random features + head-contraction trick:
//   out[h,d] = sum_i (2 * sum_f qp[h,f] kp[i,f]) * v[i,d]   (contract f FIRST)
// Emits fp16 hi/lo splits directly in the reference's reshape-quirk layout:
//   X[b, h*128 + s/16, (s%16)*128 + d]
// ============================================================================
#define TOKF (8320 + 64 + 64 + 1024 + 1024 + 2048 + 1032 + 2064 + 24 + 128)

__global__ __launch_bounds__(256)
void token_kernel(const float* __restrict__ gq, const float* __restrict__ gkv,
                  const float* __restrict__ R,
                  unsigned short* __restrict__ gxh, unsigned short* __restrict__ gxl)
{
    extern __shared__ float sm[];
    float* sRt  = sm;               // 128*65
    float* sSin = sRt + 8320;       // 64
    float* sCos = sSin + 64;        // 64
    float* sK   = sCos + 64;        // 1024
    float* sV   = sK + 1024;        // 1024
    float* sQ   = sV + 1024;        // 2048
    float* sKP  = sQ + 2048;        // 8*129
    float* sQP  = sKP + 1032;       // 16*129
    float* sN   = sQP + 2064;       // 24
    float* sA   = sN + 24;          // 128

    const int t = threadIdx.x, w = t >> 5, lane = t & 31;
    const int token = blockIdx.x, b = token >> 11, s = token & 2047;
    const float INVSF = 0.08838834764831845f;  // 1/sqrt(128)

    for (int i = t; i < 8192; i += 256) {
        int e = i >> 7, d = i & 127;
        sRt[d * 65 + e] = R[i];
    }
    if (t < 64) {
        float iv = (float)exp(-(double)t * 0.14391156831212787);  // ln(1e4)/64
        float ang = (float)s * iv;
        sincosf(ang, &sSin[t], &sCos[t]);
    }
    __syncthreads();

    // K/V/Q loads + RoPE
    {
        const int base = token * 2048;
        for (int i = t; i < 1024; i += 256) {
            int d = i & 127, j = d & 63;
            float val = gkv[base + i];
            float oth = gkv[base + (i & ~127) + ((d < 64) ? d + 64 : d - 64)];
            sK[i] = val * sCos[j] + ((d < 64) ? -oth : oth) * sSin[j];
            sV[i] = gkv[base + 1024 + i];
        }
        for (int i = t; i < 2048; i += 256) {
            int d = i & 127, j = d & 63;
            float val = gq[base + i];
            float oth = gq[base + (i & ~127) + ((d < 64) ? d + 64 : d - 64)];
            sQ[i] = val * sCos[j] + ((d < 64) ? -oth : oth) * sSin[j];
        }
    }
    __syncthreads();

    // norms: rows 0-7 = K heads, 8-23 = Q heads
    for (int r = w; r < 24; r += 8) {
        const float* src = (r < 8) ? sK + r * 128 : sQ + (r - 8) * 128;
        float ss = 0.f;
        for (int d = lane; d < 128; d += 32) { float x = src[d]; ss += x * x; }
#pragma unroll
        for (int o = 16; o; o >>= 1) ss += __shfl_xor_sync(0xffffffffu, ss, o);
        if (lane == 0) sN[r] = fmaxf(sqrtf(ss), 1e-6f);
    }
    __syncthreads();

    // projection + sin/cos features: 24 rows x 64 proj dims
#pragma unroll
    for (int it = 0; it < 6; it++) {
        int idx = it * 256 + t;
        int r = idx >> 6, e = idx & 63;
        const float* src = (r < 8) ? sK + r * 128 : sQ + (r - 8) * 128;
        float acc = 0.f;
#pragma unroll 8
        for (int d = 0; d < 128; d++) acc += src[d] * sRt[d * 65 + e];
        float p = acc / sN[r];
        float sp, cp;
        __sincosf(p, &sp, &cp);
        float* dst = (r < 8) ? sKP + r * 129 : sQP + (r - 8) * 129;
        dst[e] = sp * INVSF;
        dst[e + 64] = cp * INVSF;
    }
    __syncthreads();

    // scores A[h,i] = 2 * sum_f qp[h,f] kp[i,f]
    if (t < 128) {
        int h = t >> 3, i = t & 7;
        float acc = 0.f;
#pragma unroll 8
        for (int f = 0; f < 128; f++) acc += sQP[h * 129 + f] * sKP[i * 129 + f];
        sA[t] = 2.0f * acc;
    }
    __syncthreads();

    // out[h,d] = sum_i A[h,i] v[i,d], fp16-split, reshape-quirk scatter
    {
        const size_t obase = ((size_t)b << 22) + (size_t)((s & 15) << 7);
        const int rlo = s >> 4;
#pragma unroll
        for (int it = 0; it < 8; it++) {
            int idx = it * 256 + t;
            int h = idx >> 7, d = idx & 127;
            float acc = 0.f;
#pragma unroll
            for (int i = 0; i < 8; i++) acc += sA[h * 8 + i] * sV[i * 128 + d];
            size_t oi = obase + (size_t)(h * 128 + rlo) * 2048 + d;
            __half hv = __float2half_rn(acc);
            __half lv = __float2half_rn(acc - __half2float(hv));
            gxh[oi] = *(unsigned short*)&hv;
            gxl[oi] = *(unsigned short*)&lv;
        }
    }
}

// ============================================================================
// Launch
// ============================================================================
extern "C" void kernel_launch(void* const* d_in, const int* in_sizes, int n_in,
                              void* d_out, int out_size)
{
    const float* hs = (const float*)d_in[0];
    const float* Wq = (const float*)d_in[1];
    const float* bq = (const float*)d_in[2];
    const float* Wk = (const float*)d_in[3];
    const float* bk = (const float*)d_in[4];
    const float* Wv = (const float*)d_in[5];
    const float* bv = (const float*)d_in[6];
    const float* Wo = (const float*)d_in[7];
    const float* bo = (const float*)d_in[8];
    const float* R  = (const float*)d_in[9];
    float* out = (float*)d_out;
    (void)in_sizes; (void)n_in; (void)out_size;

    float *q, *kv;
    unsigned short *hsh, *hsl, *wqh, *wkvh, *woh, *xh, *xl;
    cudaGetSymbolAddress((void**)&q, g_q);
    cudaGetSymbolAddress((void**)&kv, g_kv);
    cudaGetSymbolAddress((void**)&hsh, g_hsh);
    cudaGetSymbolAddress((void**)&hsl, g_hsl);
    cudaGetSymbolAddress((void**)&wqh, g_wqh);
    cudaGetSymbolAddress((void**)&wkvh, g_wkvh);
    cudaGetSymbolAddress((void**)&woh, g_woh);
    cudaGetSymbolAddress((void**)&xh, g_xh);
    cudaGetSymbolAddress((void**)&xl, g_xl);

    cudaFuncSetAttribute(gemm_f16x2, cudaFuncAttributeMaxDynamicSharedMemorySize, GEMM_SMEM);
    cudaFuncSetAttribute(token_kernel, cudaFuncAttributeMaxDynamicSharedMemorySize,
                         TOKF * (int)sizeof(float));

    // input conversions
    split_f16<<<8192, 256>>>(hs, hsh, hsl, 2097152);
    convert_f16<<<4096, 256>>>(Wq, wqh, 1048576);
    convert_f16<<<2048, 256>>>(Wk, wkvh, 524288);
    convert_f16<<<2048, 256>>>(Wv, wkvh + 1024 * 2048, 524288);
    convert_f16<<<4096, 256>>>(Wo, woh, 1048576);

    // Q projection (N=2048)
    gemm_f16x2<<<dim3(8, 32), 256, GEMM_SMEM>>>(
        hsh, hsl, wqh, bq, bq, 2048, q, 4096, 2048, 2048);
    // fused K+V projection (N=2048: cols 0-1023 K w/ bk, 1024-2047 V w/ bv)
    gemm_f16x2<<<dim3(8, 32), 256, GEMM_SMEM>>>(
        hsh, hsl, wkvh, bk, bv, 1024, kv, 4096, 2048, 2048);

    // Performer core (writes fp16 splits of X)
    token_kernel<<<4096, 256, TOKF * sizeof(float)>>>(q, kv, R, xh, xl);

    // Output projection
    gemm_f16x2<<<dim3(8, 32), 256, GEMM_SMEM>>>(
        xh, xl, woh, bo, bo, 2048, out, 4096, 2048, 2048);
}

// round 5
// speedup vs baseline: 7.0466x; 1.4138x over previous
#include <cuda_runtime.h>
#include <cuda_fp16.h>
#include <cstdint>
#include <math.h>

// ============================================================================
// Scratch (allocation-free rule: __device__ globals)
// ============================================================================
__device__ float g_qkv[4096 * 4096];          // cols: 0-2047 q | 2048-3071 k | 3072-4095 v
__device__ float g_bias[4096];                // bq | bk | bv
__device__ unsigned short g_hsh[8388608];     // hs fp16
__device__ unsigned short g_wqkvh[8388608];   // Wq(2048) | Wk(1024) | Wv(1024) rows x 2048
__device__ unsigned short g_woh[4194304];
__device__ unsigned short g_xh[8388608];

// ============================================================================
// Helpers
// ============================================================================
__device__ __forceinline__ uint32_t smem_u32(const void* p) {
    uint32_t a;
    asm("{ .reg .u64 t; cvta.to.shared.u64 t, %1; cvt.u32.u64 %0, t; }" : "=r"(a) : "l"(p));
    return a;
}
__device__ __forceinline__ void cp16(uint32_t soff, const void* g) {
    asm volatile("cp.async.cg.shared.global [%0], [%1], 16;" :: "r"(soff), "l"(g));
}
__device__ __forceinline__ void cp_commit() { asm volatile("cp.async.commit_group;"); }
__device__ __forceinline__ void cp_wait0()  { asm volatile("cp.async.wait_group 0;" ::: "memory"); }
__device__ __forceinline__ void cp_wait1()  { asm volatile("cp.async.wait_group 1;" ::: "memory"); }
__device__ __forceinline__ void cp_wait2()  { asm volatile("cp.async.wait_group 2;" ::: "memory"); }
__device__ __forceinline__ void cp_wait3()  { asm volatile("cp.async.wait_group 3;" ::: "memory"); }

__device__ __forceinline__ void ldm_x4(uint32_t* r, uint32_t addr) {
    asm volatile("ldmatrix.sync.aligned.m8n8.x4.shared.b16 {%0,%1,%2,%3}, [%4];"
                 : "=r"(r[0]), "=r"(r[1]), "=r"(r[2]), "=r"(r[3]) : "r"(addr));
}
__device__ __forceinline__ void mma16816(float* c, const uint32_t* a, const uint32_t* b) {
    asm volatile(
        "mma.sync.aligned.m16n8k16.row.col.f32.f16.f16.f32 "
        "{%0,%1,%2,%3}, {%4,%5,%6,%7}, {%8,%9}, {%0,%1,%2,%3};"
        : "+f"(c[0]), "+f"(c[1]), "+f"(c[2]), "+f"(c[3])
        : "r"(a[0]), "r"(a[1]), "r"(a[2]), "r"(a[3]), "r"(b[0]), "r"(b[1]));
}

// ============================================================================
// fp32 -> fp16 convert (vectorized), and bias concat
// ============================================================================
__global__ __launch_bounds__(256)
void convert_f16(const float* __restrict__ in, unsigned short* __restrict__ hi, int n4)
{
    int i = blockIdx.x * 256 + threadIdx.x;
    if (i >= n4) return;
    float4 x = ((const float4*)in)[i];
    __half h0 = __float2half_rn(x.x), h1 = __float2half_rn(x.y);
    __half h2 = __float2half_rn(x.z), h3 = __float2half_rn(x.w);
    ushort4 H;
    H.x = *(unsigned short*)&h0;  H.y = *(unsigned short*)&h1;
    H.z = *(unsigned short*)&h2;  H.w = *(unsigned short*)&h3;
    ((ushort4*)hi)[i] = H;
}

__global__ __launch_bounds__(256)
void concat_bias(const float* __restrict__ bq, const float* __restrict__ bk,
                 const float* __restrict__ bv, float* __restrict__ gb)
{
    int i = blockIdx.x * 256 + threadIdx.x;  // 0..4095
    float v;
    if (i < 2048)      v = bq[i];
    else if (i < 3072) v = bk[i - 2048];
    else               v = bv[i - 3072];
    gb[i] = v;
}

// ============================================================================
// mma.sync fp16 1-term GEMM:  C[M,N] = Ah[M,K] @ Bh[N,K]^T + bias[N]
// Block 128x256x32, 256 threads, 8 warps (2m x 4n), warp tile 64x64.
// 4-stage cp.async pipeline, one __syncthreads per k-tile.
// ============================================================================
#define GBM 128
#define GBN 256
#define GBK 32
#define APITCH 40                       // fp16 elems/row (80 B, ldmatrix conflict-free)
#define ROW_B  (APITCH * 2)             // 80
#define OFF_B  10240                    // A: 128 rows * 80
#define STAGE_B 30720                   // + B: 256 rows * 80 (20480)
#define NSTAGE 4
#define GEMM_SMEM (NSTAGE * STAGE_B)    // 122880

__global__ __launch_bounds__(256, 1)
void gemm_f16(const unsigned short* __restrict__ Ah, const unsigned short* __restrict__ Bh,
              const float* __restrict__ bias, float* __restrict__ C,
              int M, int N, int K)
{
    extern __shared__ __align__(128) char smem[];
    const uint32_t sb = smem_u32(smem);
    const int tid = threadIdx.x, wid = tid >> 5, lane = tid & 31;
    const int bm = blockIdx.y * GBM, bn = blockIdx.x * GBN;
    const int m0w = (wid & 1) * 64, n0w = (wid >> 1) * 64;

    float c[4][8][4];
#pragma unroll
    for (int i = 0; i < 4; i++)
#pragma unroll
        for (int j = 0; j < 8; j++)
#pragma unroll
            for (int r = 0; r < 4; r++) c[i][j][r] = 0.f;

    // ldmatrix lane -> address components
    const int rowA = lane & 15, kselA = (lane >> 4) * 8;
    const int grpB = lane >> 3, rowB = lane & 7;
    const int nAdd = rowB + ((grpB & 2) ? 8 : 0);
    const int kAdd = (grpB & 1) * 8;

    const int nk = K / GBK;

    auto load_stage = [&](int kt, int buf) {
        const int k0 = kt * GBK;
        const uint32_t stb = sb + buf * STAGE_B;
#pragma unroll
        for (int it = 0; it < 6; it++) {
            int cc = it * 256 + tid;               // 0..1535
            if (cc < 512) {
                int row = cc >> 2, ch = cc & 3;
                cp16(stb + row * ROW_B + ch * 16,
                     Ah + (size_t)(bm + row) * K + k0 + ch * 8);
            } else {
                int idx = cc - 512, row = idx >> 2, ch = idx & 3;
                cp16(stb + OFF_B + row * ROW_B + ch * 16,
                     Bh + (size_t)(bn + row) * K + k0 + ch * 8);
            }
        }
    };

    load_stage(0, 0); cp_commit();
    load_stage(1, 1); cp_commit();
    load_stage(2, 2); cp_commit();

    for (int kt = 0; kt < nk; kt++) {
        if (kt + 3 <= nk)      cp_wait2();
        else if (kt + 2 == nk) cp_wait1();
        else                   cp_wait0();
        __syncthreads();

        const uint32_t stb = sb + (kt & 3) * STAGE_B;
        const uint32_t sA = stb, sB = stb + OFF_B;

#pragma unroll
        for (int kb = 0; kb < 2; kb++) {
            const int kcol = kb * 16;
            uint32_t ah[4][4];
#pragma unroll
            for (int i = 0; i < 4; i++) {
                uint32_t addr = sA + ((m0w + 16 * i + rowA) * APITCH + kcol + kselA) * 2;
                ldm_x4(ah[i], addr);
            }
            uint32_t bh[4][4];
#pragma unroll
            for (int jj = 0; jj < 4; jj++) {
                uint32_t addr = sB + ((n0w + 16 * jj + nAdd) * APITCH + kcol + kAdd) * 2;
                ldm_x4(bh[jj], addr);
            }
#pragma unroll
            for (int i = 0; i < 4; i++)
#pragma unroll
                for (int j = 0; j < 8; j++)
                    mma16816(c[i][j], ah[i], &bh[j >> 1][(j & 1) * 2]);
        }

        if (kt + 3 < nk) { load_stage(kt + 3, (kt + 3) & 3); cp_commit(); }
    }

    // epilogue: direct stores + bias
    const int r0 = lane >> 2, cc2 = (lane & 3) * 2;
#pragma unroll
    for (int i = 0; i < 4; i++) {
#pragma unroll
        for (int j = 0; j < 8; j++) {
            int row = bm + m0w + 16 * i + r0;
            int col = bn + n0w + 8 * j + cc2;
            float b0 = bias[col], b1 = bias[col + 1];
            float2 v0 = make_float2(c[i][j][0] + b0, c[i][j][1] + b1);
            float2 v1 = make_float2(c[i][j][2] + b0, c[i][j][3] + b1);
            *(float2*)&C[(size_t)row * N + col]       = v0;
            *(float2*)&C[(size_t)(row + 8) * N + col] = v1;
        }
    }
}

// ============================================================================
// Token kernel: RoPE + normalize + random features + head-contraction trick:
//   out[h,d] = sum_i (2 * sum_f qp[h,f] kp[i,f]) * v[i,d]   (contract f FIRST)
// Reads fused qkv rows [token*4096]: q@0, k@2048, v@3072.
// Emits fp16 X in the reference's reshape-quirk layout:
//   X[b, h*128 + s/16, (s%16)*128 + d]
// ============================================================================
#define TOKF (8320 + 64 + 64 + 1024 + 1024 + 2048 + 1032 + 2064 + 24 + 128)

__global__ __launch_bounds__(256)
void token_kernel(const float* __restrict__ gqkv, const float* __restrict__ R,
                  unsigned short* __restrict__ gxh)
{
    extern __shared__ float sm[];
    float* sRt  = sm;               // 128*65
    float* sSin = sRt + 8320;       // 64
    float* sCos = sSin + 64;        // 64
    float* sK   = sCos + 64;        // 1024
    float* sV   = sK + 1024;        // 1024
    float* sQ   = sV + 1024;        // 2048
    float* sKP  = sQ + 2048;        // 8*129
    float* sQP  = sKP + 1032;       // 16*129
    float* sN   = sQP + 2064;       // 24
    float* sA   = sN + 24;          // 128

    const int t = threadIdx.x, w = t >> 5, lane = t & 31;
    const int token = blockIdx.x, b = token >> 11, s = token & 2047;
    const float INVSF = 0.08838834764831845f;  // 1/sqrt(128)

    for (int i = t; i < 8192; i += 256) {
        int e = i >> 7, d = i & 127;
        sRt[d * 65 + e] = R[i];
    }
    if (t < 64) {
        float iv = (float)exp(-(double)t * 0.14391156831212787);  // ln(1e4)/64
        float ang = (float)s * iv;
        sincosf(ang, &sSin[t], &sCos[t]);
    }
    __syncthreads();

    // Q/K/V loads + RoPE (fused layout: base + {0 | 2048 | 3072})
    {
        const size_t base = (size_t)token * 4096;
        for (int i = t; i < 1024; i += 256) {
            int d = i & 127, j = d & 63;
            float val = gqkv[base + 2048 + i];
            float oth = gqkv[base + 2048 + (i & ~127) + ((d < 64) ? d + 64 : d - 64)];
            sK[i] = val * sCos[j] + ((d < 64) ? -oth : oth) * sSin[j];
            sV[i] = gqkv[base + 3072 + i];
        }
        for (int i = t; i < 2048; i += 256) {
            int d = i & 127, j = d & 63;
            float val = gqkv[base + i];
            float oth = gqkv[base + (i & ~127) + ((d < 64) ? d + 64 : d - 64)];
            sQ[i] = val * sCos[j] + ((d < 64) ? -oth : oth) * sSin[j];
        }
    }
    __syncthreads();

    // norms: rows 0-7 = K heads, 8-23 = Q heads
    for (int r = w; r < 24; r += 8) {
        const float* src = (r < 8) ? sK + r * 128 : sQ + (r - 8) * 128;
        float ss = 0.f;
        for (int d = lane; d < 128; d += 32) { float x = src[d]; ss += x * x; }
#pragma unroll
        for (int o = 16; o; o >>= 1) ss += __shfl_xor_sync(0xffffffffu, ss, o);
        if (lane == 0) sN[r] = fmaxf(sqrtf(ss), 1e-6f);
    }
    __syncthreads();

    // projection + sin/cos features: 24 rows x 64 proj dims
#pragma unroll
    for (int it = 0; it < 6; it++) {
        int idx = it * 256 + t;
        int r = idx >> 6, e = idx & 63;
        const float* src = (r < 8) ? sK + r * 128 : sQ + (r - 8) * 128;
        float acc = 0.f;
#pragma unroll 8
        for (int d = 0; d < 128; d++) acc += src[d] * sRt[d * 65 + e];
        float p = acc / sN[r];
        float sp, cp;
        __sincosf(p, &sp, &cp);
        float* dst = (r < 8) ? sKP + r * 129 : sQP + (r - 8) * 129;
        dst[e] = sp * INVSF;
        dst[e + 64] = cp * INVSF;
    }
    __syncthreads();

    // scores A[h,i] = 2 * sum_f qp[h,f] kp[i,f]
    if (t < 128) {
        int h = t >> 3, i = t & 7;
        float acc = 0.f;
#pragma unroll 8
        for (int f = 0; f < 128; f++) acc += sQP[h * 129 + f] * sKP[i * 129 + f];
        sA[t] = 2.0f * acc;
    }
    __syncthreads();

    // out[h,d] = sum_i A[h,i] v[i,d], fp16, reshape-quirk scatter
    {
        const size_t obase = ((size_t)b << 22) + (size_t)((s & 15) << 7);
        const int rlo = s >> 4;
#pragma unroll
        for (int it = 0; it < 8; it++) {
            int idx = it * 256 + t;
            int h = idx >> 7, d = idx & 127;
            float acc = 0.f;
#pragma unroll
            for (int i = 0; i < 8; i++) acc += sA[h * 8 + i] * sV[i * 128 + d];
            size_t oi = obase + (size_t)(h * 128 + rlo) * 2048 + d;
            __half hv = __float2half_rn(acc);
            gxh[oi] = *(unsigned short*)&hv;
        }
    }
}

// ============================================================================
// Launch
// ============================================================================
extern "C" void kernel_launch(void* const* d_in, const int* in_sizes, int n_in,
                              void* d_out, int out_size)
{
    const float* hs = (const float*)d_in[0];
    const float* Wq = (const float*)d_in[1];
    const float* bq = (const float*)d_in[2];
    const float* Wk = (const float*)d_in[3];
    const float* bk = (const float*)d_in[4];
    const float* Wv = (const float*)d_in[5];
    const float* bv = (const float*)d_in[6];
    const float* Wo = (const float*)d_in[7];
    const float* bo = (const float*)d_in[8];
    const float* R  = (const float*)d_in[9];
    float* out = (float*)d_out;
    (void)in_sizes; (void)n_in; (void)out_size;

    float *qkv, *gb;
    unsigned short *hsh, *wqkvh, *woh, *xh;
    cudaGetSymbolAddress((void**)&qkv, g_qkv);
    cudaGetSymbolAddress((void**)&gb, g_bias);
    cudaGetSymbolAddress((void**)&hsh, g_hsh);
    cudaGetSymbolAddress((void**)&wqkvh, g_wqkvh);
    cudaGetSymbolAddress((void**)&woh, g_woh);
    cudaGetSymbolAddress((void**)&xh, g_xh);

    cudaFuncSetAttribute(gemm_f16, cudaFuncAttributeMaxDynamicSharedMemorySize, GEMM_SMEM);
    cudaFuncSetAttribute(token_kernel, cudaFuncAttributeMaxDynamicSharedMemorySize,
                         TOKF * (int)sizeof(float));

    // conversions (fp32 -> fp16) + bias concat
    convert_f16<<<8192, 256>>>(hs, hsh, 2097152);
    convert_f16<<<4096, 256>>>(Wq, wqkvh, 1048576);
    convert_f16<<<2048, 256>>>(Wk, wqkvh + 2048 * 2048, 524288);
    convert_f16<<<2048, 256>>>(Wv, wqkvh + 3072 * 2048, 524288);
    convert_f16<<<4096, 256>>>(Wo, woh, 1048576);
    concat_bias<<<16, 256>>>(bq, bk, bv, gb);

    // fused Q+K+V projection: M=4096, N=4096, K=2048
    gemm_f16<<<dim3(16, 32), 256, GEMM_SMEM>>>(hsh, wqkvh, gb, qkv, 4096, 4096, 2048);

    // Performer core (writes fp16 X)
    token_kernel<<<4096, 256, TOKF * sizeof(float)>>>(qkv, R, xh);

    // Output projection: M=4096, N=2048, K=2048
    gemm_f16<<<dim3(8, 32), 256, GEMM_SMEM>>>(xh, woh, bo, out, 4096, 2048, 2048);
}

// round 6
// speedup vs baseline: 10.0422x; 1.4251x over previous
#include <cuda_runtime.h>
#include <cuda_fp16.h>
#include <cstdint>
#include <math.h>

// ============================================================================
// Scratch (allocation-free rule: __device__ globals)
// ============================================================================
__device__ unsigned short g_qkv[4096 * 4096];   // fp16: q 0-2047 | k 2048-3071 | v 3072-4095
__device__ float g_bias[4096];                  // bq | bk | bv
__device__ unsigned short g_hsh[8388608];       // hs fp16
__device__ unsigned short g_wqkvh[8388608];     // Wq | Wk | Wv rows x 2048
__device__ unsigned short g_woh[4194304];
__device__ unsigned short g_rh[8192];           // R fp16 [64 x 128]
__device__ unsigned short g_nx[4096 * 24 * 128];// normalized rope'd q/k rows, fp16
__device__ float g_p[4096 * 24 * 64];           // projections, fp32
__device__ unsigned short g_xh[8388608];        // X fp16 (reshape-quirk layout)

// ============================================================================
// Helpers
// ============================================================================
__device__ __forceinline__ uint32_t smem_u32(const void* p) {
    uint32_t a;
    asm("{ .reg .u64 t; cvta.to.shared.u64 t, %1; cvt.u32.u64 %0, t; }" : "=r"(a) : "l"(p));
    return a;
}
__device__ __forceinline__ void cp16(uint32_t soff, const void* g) {
    asm volatile("cp.async.cg.shared.global [%0], [%1], 16;" :: "r"(soff), "l"(g));
}
__device__ __forceinline__ void cp_commit() { asm volatile("cp.async.commit_group;"); }
__device__ __forceinline__ void cp_wait0()  { asm volatile("cp.async.wait_group 0;" ::: "memory"); }
__device__ __forceinline__ void cp_wait1()  { asm volatile("cp.async.wait_group 1;" ::: "memory"); }
__device__ __forceinline__ void cp_wait2()  { asm volatile("cp.async.wait_group 2;" ::: "memory"); }

__device__ __forceinline__ void ldm_x4(uint32_t* r, uint32_t addr) {
    asm volatile("ldmatrix.sync.aligned.m8n8.x4.shared.b16 {%0,%1,%2,%3}, [%4];"
                 : "=r"(r[0]), "=r"(r[1]), "=r"(r[2]), "=r"(r[3]) : "r"(addr));
}
__device__ __forceinline__ void mma16816(float* c, const uint32_t* a, const uint32_t* b) {
    asm volatile(
        "mma.sync.aligned.m16n8k16.row.col.f32.f16.f16.f32 "
        "{%0,%1,%2,%3}, {%4,%5,%6,%7}, {%8,%9}, {%0,%1,%2,%3};"
        : "+f"(c[0]), "+f"(c[1]), "+f"(c[2]), "+f"(c[3])
        : "r"(a[0]), "r"(a[1]), "r"(a[2]), "r"(a[3]), "r"(b[0]), "r"(b[1]));
}

__device__ __forceinline__ void store_pair(float* C, size_t off, float a, float b) {
    *(float2*)&C[off] = make_float2(a, b);
}
__device__ __forceinline__ void store_pair(__half* C, size_t off, float a, float b) {
    *(__half2*)&C[off] = __floats2half2_rn(a, b);
}

// ============================================================================
// fp32 -> fp16 convert, bias concat
// ============================================================================
__global__ __launch_bounds__(256)
void convert_f16(const float* __restrict__ in, unsigned short* __restrict__ hi, int n4)
{
    int i = blockIdx.x * 256 + threadIdx.x;
    if (i >= n4) return;
    float4 x = ((const float4*)in)[i];
    __half2 a = __floats2half2_rn(x.x, x.y);
    __half2 b = __floats2half2_rn(x.z, x.w);
    uint2 H;
    H.x = *(uint32_t*)&a;  H.y = *(uint32_t*)&b;
    ((uint2*)hi)[i] = H;
}

__global__ __launch_bounds__(256)
void concat_bias(const float* __restrict__ bq, const float* __restrict__ bk,
                 const float* __restrict__ bv, float* __restrict__ gb)
{
    int i = blockIdx.x * 256 + threadIdx.x;
    float v;
    if (i < 2048)      v = bq[i];
    else if (i < 3072) v = bk[i - 2048];
    else               v = bv[i - 3072];
    gb[i] = v;
}

// ============================================================================
// mma.sync fp16 GEMM:  C[M,N] = A[M,K] @ B[N,K]^T + bias[N]   (OutT = float | __half)
// Block 128x256x64, 256 threads, 8 warps (2m x 4n), warp tile 64x64.
// 4-stage cp.async pipeline (221 KB smem), one sync per 64-wide k-tile.
// ============================================================================
#define GBM 128
#define GBN 256
#define GBK 64
#define APITCH 72                       // fp16 elems/row: 144 B = 9x16B units, conflict-free
#define ROW_B  144
#define OFF_B  18432                    // A: 128 rows * 144
#define STAGE_B 55296                   // + B: 256 rows * 144
#define NSTAGE 4
#define GEMM_SMEM (NSTAGE * STAGE_B)    // 221184

template <typename OutT>
__global__ __launch_bounds__(256, 1)
void gemm_f16(const unsigned short* __restrict__ Ah, const unsigned short* __restrict__ Bh,
              const float* __restrict__ bias, OutT* __restrict__ C,
              int M, int N, int K)
{
    extern __shared__ __align__(128) char smem[];
    const uint32_t sb = smem_u32(smem);
    const int tid = threadIdx.x, wid = tid >> 5, lane = tid & 31;
    const int bm = blockIdx.y * GBM, bn = blockIdx.x * GBN;
    const int m0w = (wid & 1) * 64, n0w = (wid >> 1) * 64;

    float c[4][8][4];
#pragma unroll
    for (int i = 0; i < 4; i++)
#pragma unroll
        for (int j = 0; j < 8; j++)
#pragma unroll
            for (int r = 0; r < 4; r++) c[i][j][r] = 0.f;

    const int rowA = lane & 15, kselA = (lane >> 4) * 8;
    const int grpB = lane >> 3, rowB = lane & 7;
    const int nAdd = rowB + ((grpB & 2) ? 8 : 0);
    const int kAdd = (grpB & 1) * 8;

    const int nk = K / GBK;

    auto load_stage = [&](int kt, int buf) {
        const int k0 = kt * GBK;
        const uint32_t stb = sb + buf * STAGE_B;
#pragma unroll
        for (int it = 0; it < 12; it++) {
            int cc = it * 256 + tid;               // 0..3071
            if (cc < 1024) {
                int row = cc >> 3, ch = cc & 7;
                cp16(stb + row * ROW_B + ch * 16,
                     Ah + (size_t)(bm + row) * K + k0 + ch * 8);
            } else {
                int idx = cc - 1024, row = idx >> 3, ch = idx & 7;
                cp16(stb + OFF_B + row * ROW_B + ch * 16,
                     Bh + (size_t)(bn + row) * K + k0 + ch * 8);
            }
        }
    };

    load_stage(0, 0); cp_commit();
    load_stage(1, 1); cp_commit();
    load_stage(2, 2); cp_commit();

    for (int kt = 0; kt < nk; kt++) {
        if (kt + 3 <= nk)      cp_wait2();
        else if (kt + 2 == nk) cp_wait1();
        else                   cp_wait0();
        __syncthreads();

        const uint32_t stb = sb + (kt & 3) * STAGE_B;
        const uint32_t sA = stb, sB = stb + OFF_B;

#pragma unroll
        for (int kb = 0; kb < 4; kb++) {
            const int kcol = kb * 16;
            uint32_t ah[4][4];
#pragma unroll
            for (int i = 0; i < 4; i++) {
                uint32_t addr = sA + ((m0w + 16 * i + rowA) * APITCH + kcol + kselA) * 2;
                ldm_x4(ah[i], addr);
            }
            uint32_t bh[4][4];
#pragma unroll
            for (int jj = 0; jj < 4; jj++) {
                uint32_t addr = sB + ((n0w + 16 * jj + nAdd) * APITCH + kcol + kAdd) * 2;
                ldm_x4(bh[jj], addr);
            }
#pragma unroll
            for (int i = 0; i < 4; i++)
#pragma unroll
                for (int j = 0; j < 8; j++)
                    mma16816(c[i][j], ah[i], &bh[j >> 1][(j & 1) * 2]);
        }

        if (kt + 3 < nk) { load_stage(kt + 3, (kt + 3) & 3); cp_commit(); }
    }

    const int r0 = lane >> 2, cc2 = (lane & 3) * 2;
#pragma unroll
    for (int i = 0; i < 4; i++) {
#pragma unroll
        for (int j = 0; j < 8; j++) {
            int row = bm + m0w + 16 * i + r0;
            int col = bn + n0w + 8 * j + cc2;
            float b0 = bias[col], b1 = bias[col + 1];
            store_pair(C, (size_t)row * N + col,       c[i][j][0] + b0, c[i][j][1] + b1);
            store_pair(C, (size_t)(row + 8) * N + col, c[i][j][2] + b0, c[i][j][3] + b1);
        }
    }
}

// ============================================================================
// token_pre: RoPE(q,k) + row normalization -> nx[token*24 + r, 128] fp16
//   rows 0-15 = q heads, 16-23 = k heads
// ============================================================================
__global__ __launch_bounds__(256)
void token_pre(const unsigned short* __restrict__ gqkv, unsigned short* __restrict__ nx)
{
    __shared__ float sX[3072];
    __shared__ float sSin[64], sCos[64];
    __shared__ float sRinv[24];

    const int t = threadIdx.x, w = t >> 5, lane = t & 31;
    const int token = blockIdx.x, s = token & 2047;

    if (t < 64) {
        float iv = (float)exp(-(double)t * 0.14391156831212787);  // ln(1e4)/64
        float ang = (float)s * iv;
        sincosf(ang, &sSin[t], &sCos[t]);
    }
    __syncthreads();

    const size_t base = (size_t)token * 4096;
    const __half* q = (const __half*)(gqkv + base);
#pragma unroll
    for (int it = 0; it < 12; it++) {
        int i = it * 256 + t;                     // 0..3071 (q then k)
        int d = i & 127, j = d & 63;
        float val = __half2float(q[i]);
        float oth = __half2float(q[(i & ~127) + ((d < 64) ? d + 64 : d - 64)]);
        sX[i] = val * sCos[j] + ((d < 64) ? -oth : oth) * sSin[j];
    }
    __syncthreads();

    for (int r = w; r < 24; r += 8) {
        const float* src = sX + r * 128;
        float ss = 0.f;
#pragma unroll
        for (int d = lane; d < 128; d += 32) { float x = src[d]; ss += x * x; }
#pragma unroll
        for (int o = 16; o; o >>= 1) ss += __shfl_xor_sync(0xffffffffu, ss, o);
        if (lane == 0) sRinv[r] = 1.0f / fmaxf(sqrtf(ss), 1e-6f);
    }
    __syncthreads();

    unsigned short* dst = nx + (size_t)token * 3072;
#pragma unroll
    for (int it = 0; it < 6; it++) {
        int i2 = (it * 256 + t) * 2;              // pairs
        int r = i2 >> 7;
        __half2 hv = __floats2half2_rn(sX[i2] * sRinv[r], sX[i2 + 1] * sRinv[r]);
        *(__half2*)(dst + i2) = hv;
    }
}

// ============================================================================
// gemm_p: P[98304, 64] = nx[98304, 128] @ R[64, 128]^T   (one-shot K=128)
// 256 rows per CTA, 256 threads, 8 warps (4m x 2n), warp tile 64x32.
// ============================================================================
#define PP 136                           // pitch elems: 272 B = 17 units, conflict-free
#define P_OFF_B (256 * 272)              // 69632
#define P_SMEM  (P_OFF_B + 64 * 272)     // 87040

__global__ __launch_bounds__(256, 1)
void gemm_p(const unsigned short* __restrict__ nx, const unsigned short* __restrict__ Rh,
            float* __restrict__ P)
{
    extern __shared__ __align__(128) char smem[];
    const uint32_t sb = smem_u32(smem);
    const int tid = threadIdx.x, wid = tid >> 5, lane = tid & 31;
    const int bm = blockIdx.x * 256;
    const int m0w = (wid & 3) * 64, n0w = (wid >> 2) * 32;

    // load A (256 rows x 128) + R (64 rows x 128): 5120 16B chunks
#pragma unroll
    for (int it = 0; it < 20; it++) {
        int cc = it * 256 + tid;
        if (cc < 4096) {
            int row = cc >> 4, ch = cc & 15;
            cp16(sb + row * 272 + ch * 16, nx + (size_t)(bm + row) * 128 + ch * 8);
        } else {
            int idx = cc - 4096, row = idx >> 4, ch = idx & 15;
            cp16(sb + P_OFF_B + row * 272 + ch * 16, Rh + (size_t)row * 128 + ch * 8);
        }
    }
    cp_commit();
    cp_wait0();
    __syncthreads();

    const int rowA = lane & 15, kselA = (lane >> 4) * 8;
    const int grpB = lane >> 3, rowB = lane & 7;
    const int nAdd = rowB + ((grpB & 2) ? 8 : 0);
    const int kAdd = (grpB & 1) * 8;

    float c[4][4][4];
#pragma unroll
    for (int i = 0; i < 4; i++)
#pragma unroll
        for (int j = 0; j < 4; j++)
#pragma unroll
            for (int r = 0; r < 4; r++) c[i][j][r] = 0.f;

#pragma unroll
    for (int ks = 0; ks < 8; ks++) {
        const int kcol = ks * 16;
        uint32_t ah[4][4];
#pragma unroll
        for (int i = 0; i < 4; i++) {
            uint32_t addr = sb + ((m0w + 16 * i + rowA) * PP + kcol + kselA) * 2;
            ldm_x4(ah[i], addr);
        }
        uint32_t bh[2][4];
#pragma unroll
        for (int jj = 0; jj < 2; jj++) {
            uint32_t addr = sb + P_OFF_B + ((n0w + 16 * jj + nAdd) * PP + kcol + kAdd) * 2;
            ldm_x4(bh[jj], addr);
        }
#pragma unroll
        for (int i = 0; i < 4; i++)
#pragma unroll
            for (int j = 0; j < 4; j++)
                mma16816(c[i][j], ah[i], &bh[j >> 1][(j & 1) * 2]);
    }

    const int r0 = lane >> 2, cc2 = (lane & 3) * 2;
#pragma unroll
    for (int i = 0; i < 4; i++) {
#pragma unroll
        for (int j = 0; j < 4; j++) {
            int row = bm + m0w + 16 * i + r0;
            int col = n0w + 8 * j + cc2;
            *(float2*)&P[(size_t)row * 64 + col]       = make_float2(c[i][j][0], c[i][j][1]);
            *(float2*)&P[(size_t)(row + 8) * 64 + col] = make_float2(c[i][j][2], c[i][j][3]);
        }
    }
}

// ============================================================================
// token_post: feats = sincos(P)/sqrt(F); scores A[h,i] = 2*qp.kp; out = A @ V
// Emits fp16 X in the reference's reshape-quirk layout:
//   X[b, h*128 + s/16, (s%16)*128 + d]
// ============================================================================
__global__ __launch_bounds__(256)
void token_post(const float* __restrict__ gP, const unsigned short* __restrict__ gqkv,
                unsigned short* __restrict__ gxh)
{
    __shared__ float sQP[16 * 129];
    __shared__ float sKP[8 * 129];
    __shared__ float sV[1024];
    __shared__ float sA[128];

    const int t = threadIdx.x;
    const int token = blockIdx.x, b = token >> 11, s = token & 2047;
    const float INVSF = 0.08838834764831845f;  // 1/sqrt(128)

    // feats from P (rows 0-15 q, 16-23 k)
    const float* P = gP + (size_t)token * 1536;
#pragma unroll
    for (int it = 0; it < 6; it++) {
        int i = it * 256 + t;                  // 0..1535
        int r = i >> 6, e = i & 63;
        float p = P[i];
        float sp, cp;
        __sincosf(p, &sp, &cp);
        float* dst = (r < 16) ? sQP + r * 129 : sKP + (r - 16) * 129;
        dst[e] = sp * INVSF;
        dst[e + 64] = cp * INVSF;
    }
    // V
    const __half* v = (const __half*)(gqkv + (size_t)token * 4096 + 3072);
#pragma unroll
    for (int it = 0; it < 4; it++) {
        int i = it * 256 + t;
        sV[i] = __half2float(v[i]);
    }
    __syncthreads();

    // scores
    if (t < 128) {
        int h = t >> 3, i = t & 7;
        float acc = 0.f;
#pragma unroll 8
        for (int f = 0; f < 128; f++) acc += sQP[h * 129 + f] * sKP[i * 129 + f];
        sA[t] = 2.0f * acc;
    }
    __syncthreads();

    // out + scatter
    const size_t obase = ((size_t)b << 22) + (size_t)((s & 15) << 7);
    const int rlo = s >> 4;
#pragma unroll
    for (int it = 0; it < 8; it++) {
        int idx = it * 256 + t;
        int h = idx >> 7, d = idx & 127;
        float acc = 0.f;
#pragma unroll
        for (int i = 0; i < 8; i++) acc += sA[h * 8 + i] * sV[i * 128 + d];
        size_t oi = obase + (size_t)(h * 128 + rlo) * 2048 + d;
        __half hv = __float2half_rn(acc);
        gxh[oi] = *(unsigned short*)&hv;
    }
}

// ============================================================================
// Launch
// ============================================================================
extern "C" void kernel_launch(void* const* d_in, const int* in_sizes, int n_in,
                              void* d_out, int out_size)
{
    const float* hs = (const float*)d_in[0];
    const float* Wq = (const float*)d_in[1];
    const float* bq = (const float*)d_in[2];
    const float* Wk = (const float*)d_in[3];
    const float* bk = (const float*)d_in[4];
    const float* Wv = (const float*)d_in[5];
    const float* bv = (const float*)d_in[6];
    const float* Wo = (const float*)d_in[7];
    const float* bo = (const float*)d_in[8];
    const float* R  = (const float*)d_in[9];
    float* out = (float*)d_out;
    (void)in_sizes; (void)n_in; (void)out_size;

    unsigned short *qkv, *hsh, *wqkvh, *woh, *rh, *nx, *xh;
    float *gb, *gp;
    cudaGetSymbolAddress((void**)&qkv, g_qkv);
    cudaGetSymbolAddress((void**)&gb, g_bias);
    cudaGetSymbolAddress((void**)&hsh, g_hsh);
    cudaGetSymbolAddress((void**)&wqkvh, g_wqkvh);
    cudaGetSymbolAddress((void**)&woh, g_woh);
    cudaGetSymbolAddress((void**)&rh, g_rh);
    cudaGetSymbolAddress((void**)&nx, g_nx);
    cudaGetSymbolAddress((void**)&gp, g_p);
    cudaGetSymbolAddress((void**)&xh, g_xh);

    cudaFuncSetAttribute(gemm_f16<float>, cudaFuncAttributeMaxDynamicSharedMemorySize, GEMM_SMEM);
    cudaFuncSetAttribute(gemm_f16<__half>, cudaFuncAttributeMaxDynamicSharedMemorySize, GEMM_SMEM);
    cudaFuncSetAttribute(gemm_p, cudaFuncAttributeMaxDynamicSharedMemorySize, P_SMEM);

    // conversions
    convert_f16<<<8192, 256>>>(hs, hsh, 2097152);
    convert_f16<<<4096, 256>>>(Wq, wqkvh, 1048576);
    convert_f16<<<2048, 256>>>(Wk, wqkvh + 2048 * 2048, 524288);
    convert_f16<<<2048, 256>>>(Wv, wqkvh + 3072 * 2048, 524288);
    convert_f16<<<4096, 256>>>(Wo, woh, 1048576);
    convert_f16<<<8, 256>>>(R, rh, 2048);
    concat_bias<<<16, 256>>>(bq, bk, bv, gb);

    // fused Q+K+V projection (fp16 out)
    gemm_f16<__half><<<dim3(16, 32), 256, GEMM_SMEM>>>(
        hsh, wqkvh, gb, (__half*)qkv, 4096, 4096, 2048);

    // performer core: RoPE+norm -> projection GEMM -> feats/scores/out
    token_pre<<<4096, 256>>>(qkv, nx);
    gemm_p<<<384, 256, P_SMEM>>>(nx, rh, gp);
    token_post<<<4096, 256>>>(gp, qkv, xh);

    // output projection (fp32 out)
    gemm_f16<float><<<dim3(8, 32), 256, GEMM_SMEM>>>(
        xh, woh, bo, out, 4096, 2048, 2048);
}